// round 4
// baseline (speedup 1.0000x reference)
#include <cuda_runtime.h>
#include <math.h>

typedef unsigned long long u64;

__device__ __forceinline__ u64 pk2(float lo, float hi) {
    u64 r; asm("mov.b64 %0, {%1, %2};" : "=l"(r) : "f"(lo), "f"(hi)); return r;
}
__device__ __forceinline__ void upk2(u64 v, float& lo, float& hi) {
    asm("mov.b64 {%0, %1}, %2;" : "=f"(lo), "=f"(hi) : "l"(v));
}
__device__ __forceinline__ u64 fma2(u64 a, u64 b, u64 c) {
    u64 d; asm("fma.rn.f32x2 %0, %1, %2, %3;" : "=l"(d) : "l"(a), "l"(b), "l"(c)); return d;
}
__device__ __forceinline__ u64 add2(u64 a, u64 b) {
    u64 d; asm("add.rn.f32x2 %0, %1, %2;" : "=l"(d) : "l"(a), "l"(b)); return d;
}
__device__ __forceinline__ float ex2f(float x) {
    float e; asm("ex2.approx.ftz.f32 %0, %1;" : "=f"(e) : "f"(x)); return e;
}

#define MAGIC_F 12582912.0f   // 1.5 * 2^23

// grid = (M/64, B), 64 threads. One kernel: stages + preprocesses samples in
// smem, computes point constants per-thread, hybrid MUFU/poly exp2 mainloop.
__global__ __launch_bounds__(64)
void kde_main_kernel(const float* __restrict__ inputs,
                     const float* __restrict__ pts,
                     float* __restrict__ out,
                     int N, int M, float gamma2, float scale_out) {
    const int b = blockIdx.y;
    const int m = blockIdx.x * 64 + threadIdx.x;

    __shared__ float sxx[2048], sxy[2048], ssn[2048];

    // Stage + preprocess samples of batch b: (B,N,2) -> SoA (xx, xy, -g2*|x|^2)
    {
        const float4* src = (const float4*)(inputs + (size_t)b * N * 2);
        const int nv = N >> 1;          // float4s, 2 samples each
        for (int j = threadIdx.x; j < nv; j += 64) {
            float4 v = src[j];
            int n0 = 2 * j;
            sxx[n0]     = v.x;  sxy[n0]     = v.y;
            ssn[n0]     = -gamma2 * fmaf(v.x, v.x, v.y * v.y);
            sxx[n0 + 1] = v.z;  sxy[n0 + 1] = v.w;
            ssn[n0 + 1] = -gamma2 * fmaf(v.z, v.z, v.w * v.w);
        }
    }

    // Point constants (log2 units): arg = am2 + qx*xx + qy*xy + sn
    const float px = pts[2 * m], py = pts[2 * m + 1];
    const float qxs = 2.0f * gamma2 * px;
    const float qys = 2.0f * gamma2 * py;
    const float am2s = -gamma2 * fmaf(px, px, py * py);

    __syncthreads();

    const u64 qx2  = pk2(qxs, qxs);
    const u64 qy2  = pk2(qys, qys);
    const u64 am22 = pk2(am2s, am2s);

    // exp2 poly coeffs (deg 5, f in [-0.5, 0.5]) packed
    const u64 C0 = pk2(1.0f, 1.0f);
    const u64 C1 = pk2(0.69314718056f, 0.69314718056f);
    const u64 C2 = pk2(0.24022650696f, 0.24022650696f);
    const u64 C3 = pk2(0.05550410866f, 0.05550410866f);
    const u64 C4 = pk2(0.00961812911f, 0.00961812911f);
    const u64 C5 = pk2(0.00133335581f, 0.00133335581f);
    const u64 MG   = pk2(MAGIC_F, MAGIC_F);
    const u64 NMG  = pk2(-MAGIC_F, -MAGIC_F);
    const u64 NONE = pk2(-1.0f, -1.0f);

    u64 accM0 = 0ull, accM1 = 0ull, accM2 = 0ull, accP = 0ull;

    const float4* hx = (const float4*)sxx;
    const float4* hy = (const float4*)sxy;
    const float4* hs = (const float4*)ssn;

    const int nq = N >> 3;   // iterations of 8 samples (2 float4 sets)
    #pragma unroll 4
    for (int q = 0; q < nq; q++) {
        int j = 2 * q;
        float4 X0 = hx[j],     Y0 = hy[j],     S0 = hs[j];
        float4 X1 = hx[j + 1], Y1 = hy[j + 1], S1 = hs[j + 1];

        // dot products (3 packed fma-pipe ops per pair)
        u64 ta = fma2(qx2, pk2(X0.x, X0.y), am22);
        ta = fma2(qy2, pk2(Y0.x, Y0.y), ta);
        ta = add2(ta, pk2(S0.x, S0.y));

        u64 tb = fma2(qx2, pk2(X0.z, X0.w), am22);
        tb = fma2(qy2, pk2(Y0.z, Y0.w), tb);
        tb = add2(tb, pk2(S0.z, S0.w));

        u64 tc = fma2(qx2, pk2(X1.x, X1.y), am22);
        tc = fma2(qy2, pk2(Y1.x, Y1.y), tc);
        tc = add2(tc, pk2(S1.x, S1.y));

        u64 td = fma2(qx2, pk2(X1.z, X1.w), am22);
        td = fma2(qy2, pk2(Y1.z, Y1.w), td);
        td = add2(td, pk2(S1.z, S1.w));

        // 3 pairs via MUFU ex2
        float a0, a1, b0, b1, c0, c1;
        upk2(ta, a0, a1);
        upk2(tb, b0, b1);
        upk2(tc, c0, c1);
        accM0 = add2(accM0, pk2(ex2f(a0), ex2f(a1)));
        accM1 = add2(accM1, pk2(ex2f(b0), ex2f(b1)));
        accM2 = add2(accM2, pk2(ex2f(c0), ex2f(c1)));

        // 1 pair via packed polynomial exp2 (FMA pipe + ALU)
        float d0, d1;
        upk2(td, d0, d1);
        d0 = fmaxf(d0, -125.0f);            // underflow clamp (FMNMX, ALU pipe)
        d1 = fmaxf(d1, -125.0f);
        u64 tdc = pk2(d0, d1);
        u64 k2 = add2(tdc, MG);             // round-to-int in mantissa
        u64 n2 = add2(k2, NMG);             // n = rint(t)
        u64 f2 = fma2(NONE, n2, tdc);       // f = t - n, f in [-0.5, 0.5]
        u64 p2 = fma2(C5, f2, C4);
        p2 = fma2(p2, f2, C3);
        p2 = fma2(p2, f2, C2);
        p2 = fma2(p2, f2, C1);
        p2 = fma2(p2, f2, C0);
        float kf0, kf1;
        upk2(k2, kf0, kf1);
        // k_bits = 0x4B400000 + n  ->  2^n bits = (k_bits << 23) + 0x3F800000
        int s0b = (__float_as_int(kf0) << 23) + 0x3F800000;
        int s1b = (__float_as_int(kf1) << 23) + 0x3F800000;
        u64 s2 = pk2(__int_as_float(s0b), __int_as_float(s1b));
        accP = fma2(p2, s2, accP);          // acc += poly * 2^n
    }

    float r0, r1, r2, r3, r4, r5, r6, r7;
    upk2(accM0, r0, r1);
    upk2(accM1, r2, r3);
    upk2(accM2, r4, r5);
    upk2(accP,  r6, r7);
    float total = ((r0 + r1) + (r2 + r3)) + ((r4 + r5) + (r6 + r7));
    out[(size_t)b * M + m] = total * scale_out;
}

extern "C" void kernel_launch(void* const* d_in, const int* in_sizes, int n_in,
                              void* d_out, int out_size) {
    const float* inputs = (const float*)d_in[0];   // (B, N, 2) float32
    const float* pts    = (const float*)d_in[1];   // (M, 2) float32
    float* out          = (float*)d_out;           // (B, M) float32

    const int d = 2;
    const int M  = in_sizes[1] / d;                // 512
    const int BN = in_sizes[0] / d;                // B*N
    const int B  = out_size / M;                   // 128
    const int N  = BN / B;                         // 2048

    // Silverman bandwidth (d=2)
    double h = pow(4.0 / (d + 2), 1.0 / (d + 4)) * pow((double)N, -1.0 / (d + 4));
    double coef = 1.0 / pow(2.0 * M_PI * h * h, d / 2.0);
    double gamma = 0.5 / (h * h);
    float gamma2 = (float)(gamma * 1.4426950408889634);  // fold 1/ln2 for ex2
    float scale_out = (float)(coef / (double)N);

    dim3 grid(M / 64, B);   // (8, 128) = 1024 blocks, 64 threads
    kde_main_kernel<<<grid, 64>>>(inputs, pts, out, N, M, gamma2, scale_out);
}